// round 2
// baseline (speedup 1.0000x reference)
#include <cuda_runtime.h>
#include <cuda_bf16.h>
#include <cstdint>

#define Bn 8192
#define Mn 64
#define Dn 256

__device__ float g_r[(size_t)Bn * Dn];

// ---------------------------------------------------------------------------
// PTX helpers (mbarrier + 1D TMA bulk copy)
// ---------------------------------------------------------------------------
__device__ __forceinline__ uint32_t smem_u32(const void* p) {
    uint32_t a;
    asm("{ .reg .u64 t; cvta.to.shared.u64 t, %1; cvt.u32.u64 %0, t; }"
        : "=r"(a) : "l"(p));
    return a;
}
__device__ __forceinline__ void mbar_init(uint32_t a, uint32_t cnt) {
    asm volatile("mbarrier.init.shared.b64 [%0], %1;" :: "r"(a), "r"(cnt) : "memory");
}
__device__ __forceinline__ void mbar_expect_tx(uint32_t a, uint32_t bytes) {
    asm volatile("mbarrier.arrive.expect_tx.shared.b64 _, [%0], %1;"
                 :: "r"(a), "r"(bytes) : "memory");
}
__device__ __forceinline__ void bulk_g2s(uint32_t dst, const void* src,
                                         uint32_t bytes, uint32_t mbar) {
    asm volatile("cp.async.bulk.shared::cta.global.mbarrier::complete_tx::bytes "
                 "[%0], [%1], %2, [%3];"
                 :: "r"(dst), "l"(src), "r"(bytes), "r"(mbar) : "memory");
}
__device__ __forceinline__ void mbar_wait(uint32_t a, uint32_t parity) {
    asm volatile(
        "{\n\t.reg .pred P;\n"
        "W%=:\n\t"
        "mbarrier.try_wait.parity.shared::cta.b64 P, [%0], %1;\n\t"
        "@!P bra W%=;\n\t}"
        :: "r"(a), "r"(parity) : "memory");
}

// ---------------------------------------------------------------------------
// Kernel 1: persistent attention. 148 CTAs (1/SM), 512 threads.
// Double-buffered 64KB mem[b] tiles via TMA bulk copy; compute overlaps load.
// ---------------------------------------------------------------------------
#define ATTN_CTAS 148
#define ATTN_THREADS 512

// dynamic smem layout (bytes)
#define BUF0_OFF   0
#define BUF1_OFF   65536
#define H_OFF      131072          // 256 floats
#define SC_OFF     132096          // 64 floats
#define PS_OFF     132352          // 256 floats
#define MBAR_OFF   133376          // 2 x 8B
#define ATTN_SMEM  133408

__global__ __launch_bounds__(ATTN_THREADS, 1) void attn_kernel(
    const float* __restrict__ h,
    const float* __restrict__ mem,
    const int*   __restrict__ lengths,
    float*       __restrict__ r_out)
{
    extern __shared__ char smem[];
    float* bufp[2] = { (float*)(smem + BUF0_OFF), (float*)(smem + BUF1_OFF) };
    float* h_s  = (float*)(smem + H_OFF);
    float* sc   = (float*)(smem + SC_OFF);
    float* psum = (float*)(smem + PS_OFF);

    const uint32_t sbase = smem_u32(smem);
    const uint32_t bufa[2] = { sbase + BUF0_OFF, sbase + BUF1_OFF };
    const uint32_t mba[2]  = { sbase + MBAR_OFF, sbase + MBAR_OFF + 8 };

    const int tid  = threadIdx.x;
    const int lane = tid & 31;
    const int warp = tid >> 5;

    if (tid == 0) { mbar_init(mba[0], 1); mbar_init(mba[1], 1); }
    __syncthreads();

    int phase[2] = {0, 0};
    int cur = 0;

    const int b0 = blockIdx.x;
    if (tid == 0 && b0 < Bn) {
        mbar_expect_tx(mba[0], Mn * Dn * 4);
        bulk_g2s(bufa[0], mem + (size_t)b0 * Mn * Dn, Mn * Dn * 4, mba[0]);
    }

    for (int b = b0; b < Bn; b += ATTN_CTAS) {
        const int nb = b + ATTN_CTAS;
        if (tid == 0 && nb < Bn) {
            mbar_expect_tx(mba[cur ^ 1], Mn * Dn * 4);
            bulk_g2s(bufa[cur ^ 1], mem + (size_t)nb * Mn * Dn, Mn * Dn * 4,
                     mba[cur ^ 1]);
        }
        if (tid < Dn) h_s[tid] = h[(size_t)b * Dn + tid];

        mbar_wait(mba[cur], phase[cur]);
        phase[cur] ^= 1;
        __syncthreads();

        const float* mb = bufp[cur];

        // scores: warp w handles rows 4w..4w+3; lane covers 8 contiguous floats
#pragma unroll
        for (int j = 0; j < 4; ++j) {
            const int m = warp * 4 + j;
            const float4* row = (const float4*)(mb + m * Dn);
            const float4* hv  = (const float4*)h_s;
            float s = 0.f;
#pragma unroll
            for (int q = 0; q < 2; ++q) {
                const float4 a = row[lane * 2 + q];
                const float4 c = hv[lane * 2 + q];
                s = fmaf(a.x, c.x, s); s = fmaf(a.y, c.y, s);
                s = fmaf(a.z, c.z, s); s = fmaf(a.w, c.w, s);
            }
#pragma unroll
            for (int off = 16; off; off >>= 1)
                s += __shfl_xor_sync(0xffffffffu, s, off);
            if (lane == 0) sc[m] = s;
        }
        __syncthreads();

        // masked softmax (warp 0)
        if (warp == 0) {
            const int len = lengths[b];
            float a0 = (lane      < len) ? sc[lane]      : -1e9f;
            float a1 = (lane + 32 < len) ? sc[lane + 32] : -1e9f;
            float mx = fmaxf(a0, a1);
#pragma unroll
            for (int off = 16; off; off >>= 1)
                mx = fmaxf(mx, __shfl_xor_sync(0xffffffffu, mx, off));
            float e0 = __expf(a0 - mx);
            float e1 = __expf(a1 - mx);
            float s  = e0 + e1;
#pragma unroll
            for (int off = 16; off; off >>= 1)
                s += __shfl_xor_sync(0xffffffffu, s, off);
            const float inv = 1.f / s;
            sc[lane]      = e0 * inv;
            sc[lane + 32] = e1 * inv;
        }
        __syncthreads();

        // weighted sum, split over m halves
        {
            const int part = tid >> 8;     // 0 or 1
            const int d    = tid & 255;
            float acc = 0.f;
            const int m0 = part * 32;
#pragma unroll
            for (int m = 0; m < 32; ++m)
                acc = fmaf(sc[m0 + m], mb[(m0 + m) * Dn + d], acc);
            if (part) psum[d] = acc;
            __syncthreads();
            if (!part) r_out[(size_t)b * Dn + d] = acc + psum[d];
        }
        __syncthreads();   // all done with mb/sc/psum before reuse
        cur ^= 1;
    }
}

// ---------------------------------------------------------------------------
// Kernel 2: 128x128x8 SGEMM ([h|r] @ [Wg|Ug]^T), 8x8 micro-tile, double-
// buffered smem, fused sigmoid-gate epilogue. Grid = 128 CTAs (one wave).
// ---------------------------------------------------------------------------
#define GBM 128
#define GBN 128
#define GBK 8

__global__ __launch_bounds__(256) void gemm_fuse_kernel(
    const float* __restrict__ hA,
    const float* __restrict__ rA,
    const float* __restrict__ Wg,
    const float* __restrict__ Ug,
    const float* __restrict__ Wgb,
    const float* __restrict__ Ugb,
    const float* __restrict__ bg,
    const int*   __restrict__ lengths,
    float*       __restrict__ out)
{
    __shared__ float As[2][GBK][GBM];
    __shared__ float Bs[2][GBK][GBN];

    const int tid = threadIdx.x;
    const int tx  = tid & 15;
    const int ty  = tid >> 4;
    const int rbase = blockIdx.y * GBM;
    const int cbase = blockIdx.x * GBN;

    const int lr = tid >> 1;          // 0..127
    const int lk = (tid & 1) * 4;     // 0 or 4

    float acc[8][8] = {};

    // prefetch tile 0 (from h / Wg)
    float4 pa = *(const float4*)&hA[(size_t)(rbase + lr) * Dn + lk];
    float4 pb = *(const float4*)&Wg[(size_t)(cbase + lr) * Dn + lk];
    As[0][lk + 0][lr] = pa.x; As[0][lk + 1][lr] = pa.y;
    As[0][lk + 2][lr] = pa.z; As[0][lk + 3][lr] = pa.w;
    Bs[0][lk + 0][lr] = pb.x; Bs[0][lk + 1][lr] = pb.y;
    Bs[0][lk + 2][lr] = pb.z; Bs[0][lk + 3][lr] = pb.w;
    __syncthreads();

    int buf = 0;
#pragma unroll 1
    for (int kt = 0; kt < 64; ++kt) {
        if (kt < 63) {
            const int t = kt + 1;
            const float* Ap = (t < 32) ? hA : rA;
            const float* Bp = (t < 32) ? Wg : Ug;
            const int kb = (t & 31) * GBK;
            pa = *(const float4*)&Ap[(size_t)(rbase + lr) * Dn + kb + lk];
            pb = *(const float4*)&Bp[(size_t)(cbase + lr) * Dn + kb + lk];
        }
#pragma unroll
        for (int k = 0; k < GBK; ++k) {
            const float4 a0 = *(const float4*)&As[buf][k][ty * 4];
            const float4 a1 = *(const float4*)&As[buf][k][64 + ty * 4];
            const float4 b0 = *(const float4*)&Bs[buf][k][tx * 4];
            const float4 b1 = *(const float4*)&Bs[buf][k][64 + tx * 4];
            const float ar[8] = {a0.x, a0.y, a0.z, a0.w, a1.x, a1.y, a1.z, a1.w};
            const float br[8] = {b0.x, b0.y, b0.z, b0.w, b1.x, b1.y, b1.z, b1.w};
#pragma unroll
            for (int i = 0; i < 8; ++i)
#pragma unroll
                for (int j = 0; j < 8; ++j)
                    acc[i][j] = fmaf(ar[i], br[j], acc[i][j]);
        }
        if (kt < 63) {
            const int nb = buf ^ 1;
            As[nb][lk + 0][lr] = pa.x; As[nb][lk + 1][lr] = pa.y;
            As[nb][lk + 2][lr] = pa.z; As[nb][lk + 3][lr] = pa.w;
            Bs[nb][lk + 0][lr] = pb.x; Bs[nb][lk + 1][lr] = pb.y;
            Bs[nb][lk + 2][lr] = pb.z; Bs[nb][lk + 3][lr] = pb.w;
            __syncthreads();
            buf = nb;
        }
    }

    // epilogue
    float zb[8];
#pragma unroll
    for (int j = 0; j < 8; ++j) {
        const int d = cbase + (j < 4 ? tx * 4 + j : 64 + tx * 4 + j - 4);
        zb[j] = Wgb[d] + Ugb[d] + bg[d];
    }

#pragma unroll
    for (int i = 0; i < 8; ++i) {
        const int row = (i < 4) ? ty * 4 + i : 64 + ty * 4 + i - 4;
        const int b   = rbase + row;
        const int len = lengths[b];
#pragma unroll
        for (int jj = 0; jj < 2; ++jj) {
            const int c0 = cbase + jj * 64 + tx * 4;
            const float4 rv = *(const float4*)&rA[(size_t)b * Dn + c0];
            const float4 hv = *(const float4*)&hA[(size_t)b * Dn + c0];
            const float rr[4] = {rv.x, rv.y, rv.z, rv.w};
            const float hh[4] = {hv.x, hv.y, hv.z, hv.w};
            float4 o;
            float* op = &o.x;
#pragma unroll
            for (int j = 0; j < 4; ++j) {
                const float z = acc[i][jj * 4 + j] + zb[jj * 4 + j];
                const float g = 1.f / (1.f + __expf(-z));
                const float fused = g * rr[j] + (1.f - g) * hh[j];
                op[j] = (len > 0) ? fused : hh[j];
            }
            *(float4*)&out[(size_t)b * Dn + c0] = o;
        }
    }
}

// ---------------------------------------------------------------------------
extern "C" void kernel_launch(void* const* d_in, const int* in_sizes, int n_in,
                              void* d_out, int out_size)
{
    const float* h_tilde = (const float*)d_in[0];
    const float* mem     = (const float*)d_in[1];
    const int*   lengths = (const int*)  d_in[2];
    const float* Wg_w    = (const float*)d_in[3];
    const float* Wg_b    = (const float*)d_in[4];
    const float* Ug_w    = (const float*)d_in[5];
    const float* Ug_b    = (const float*)d_in[6];
    const float* b_g     = (const float*)d_in[7];
    float* out = (float*)d_out;

    float* r_ptr = nullptr;
    cudaGetSymbolAddress((void**)&r_ptr, g_r);

    cudaFuncSetAttribute(attn_kernel,
                         cudaFuncAttributeMaxDynamicSharedMemorySize, ATTN_SMEM);

    attn_kernel<<<ATTN_CTAS, ATTN_THREADS, ATTN_SMEM>>>(h_tilde, mem, lengths,
                                                        r_ptr);

    dim3 grid(Dn / GBN, Bn / GBM);  // (2, 64) = 128 CTAs
    gemm_fuse_kernel<<<grid, 256>>>(h_tilde, r_ptr, Wg_w, Ug_w,
                                    Wg_b, Ug_b, b_g, lengths, out);
}

// round 8
// speedup vs baseline: 1.3435x; 1.3435x over previous
#include <cuda_runtime.h>
#include <cuda_bf16.h>
#include <cstdint>

#define Bn 8192
#define Mn 64
#define Dn 256
#define Kn 512

__device__ __align__(16) float         g_r  [(size_t)Bn * Dn];
__device__ __align__(16) __nv_bfloat16 g_Ahi[(size_t)Bn * Kn];
__device__ __align__(16) __nv_bfloat16 g_Alo[(size_t)Bn * Kn];
__device__ __align__(16) __nv_bfloat16 g_Bhi[(size_t)Dn * Kn];
__device__ __align__(16) __nv_bfloat16 g_Blo[(size_t)Dn * Kn];

// ---------------------------------------------------------------------------
__device__ __forceinline__ uint32_t smem_u32(const void* p) {
    uint32_t a;
    asm("{ .reg .u64 t; cvta.to.shared.u64 t, %1; cvt.u32.u64 %0, t; }"
        : "=r"(a) : "l"(p));
    return a;
}
__device__ __forceinline__ void cp16(uint32_t dst, const void* src) {
    asm volatile("cp.async.cg.shared.global [%0], [%1], 16;"
                 :: "r"(dst), "l"(src) : "memory");
}
__device__ __forceinline__ void cp_commit() {
    asm volatile("cp.async.commit_group;" ::: "memory");
}
template <int N>
__device__ __forceinline__ void cp_wait() {
    asm volatile("cp.async.wait_group %0;" :: "n"(N) : "memory");
}
__device__ __forceinline__ void mma16816(float& d0, float& d1, float& d2, float& d3,
                                         uint32_t a0, uint32_t a1, uint32_t a2,
                                         uint32_t a3, uint32_t b0, uint32_t b1) {
    asm volatile(
        "mma.sync.aligned.m16n8k16.row.col.f32.bf16.bf16.f32 "
        "{%0,%1,%2,%3}, {%4,%5,%6,%7}, {%8,%9}, {%0,%1,%2,%3};"
        : "+f"(d0), "+f"(d1), "+f"(d2), "+f"(d3)
        : "r"(a0), "r"(a1), "r"(a2), "r"(a3), "r"(b0), "r"(b1));
}

// ---------------------------------------------------------------------------
// Kernel 1: attention (round-1 proven) + bf16 hi/lo split epilogue.
// ---------------------------------------------------------------------------
__global__ __launch_bounds__(256) void attn_kernel(
    const float* __restrict__ h,
    const float* __restrict__ mem,
    const int*   __restrict__ lengths,
    float*       __restrict__ r_out,
    __nv_bfloat16* __restrict__ Ahi,
    __nv_bfloat16* __restrict__ Alo)
{
    extern __shared__ float smem[];
    float* mem_s = smem;
    float* h_s   = smem + Mn * Dn;
    float* sc    = h_s + Dn;

    const int b    = blockIdx.x;
    const int tid  = threadIdx.x;
    const int lane = tid & 31;
    const int warp = tid >> 5;

    h_s[tid] = h[(size_t)b * Dn + tid];
    const float4* msrc = (const float4*)(mem + (size_t)b * Mn * Dn);
    float4*       mdst = (float4*)mem_s;
#pragma unroll
    for (int i = 0; i < (Mn * Dn / 4) / 256; ++i)
        mdst[tid + 256 * i] = msrc[tid + 256 * i];
    __syncthreads();

#pragma unroll
    for (int j = 0; j < 8; ++j) {
        const int m = warp * 8 + j;
        const float* row = mem_s + m * Dn;
        float s = 0.f;
#pragma unroll
        for (int kk = 0; kk < Dn / 32; ++kk)
            s = fmaf(row[lane + 32 * kk], h_s[lane + 32 * kk], s);
#pragma unroll
        for (int off = 16; off; off >>= 1)
            s += __shfl_xor_sync(0xffffffffu, s, off);
        if (lane == 0) sc[m] = s;
    }
    __syncthreads();

    if (warp == 0) {
        const int len = lengths[b];
        float a0 = (lane      < len) ? sc[lane]      : -1e9f;
        float a1 = (lane + 32 < len) ? sc[lane + 32] : -1e9f;
        float mx = fmaxf(a0, a1);
#pragma unroll
        for (int off = 16; off; off >>= 1)
            mx = fmaxf(mx, __shfl_xor_sync(0xffffffffu, mx, off));
        float e0 = __expf(a0 - mx);
        float e1 = __expf(a1 - mx);
        float s  = e0 + e1;
#pragma unroll
        for (int off = 16; off; off >>= 1)
            s += __shfl_xor_sync(0xffffffffu, s, off);
        const float inv = 1.f / s;
        sc[lane]      = e0 * inv;
        sc[lane + 32] = e1 * inv;
    }
    __syncthreads();

    float acc = 0.f;
#pragma unroll
    for (int m = 0; m < Mn; ++m)
        acc = fmaf(sc[m], mem_s[m * Dn + tid], acc);
    r_out[(size_t)b * Dn + tid] = acc;

    {
        const float xh = h_s[tid];
        const __nv_bfloat16 hh = __float2bfloat16(xh);
        Ahi[(size_t)b * Kn + tid] = hh;
        Alo[(size_t)b * Kn + tid] = __float2bfloat16(xh - __bfloat162float(hh));
        const __nv_bfloat16 rh = __float2bfloat16(acc);
        Ahi[(size_t)b * Kn + Dn + tid] = rh;
        Alo[(size_t)b * Kn + Dn + tid] = __float2bfloat16(acc - __bfloat162float(rh));
    }
}

// ---------------------------------------------------------------------------
// Kernel 2: weight concat + bf16 hi/lo split.
// ---------------------------------------------------------------------------
__global__ __launch_bounds__(512) void wconv_kernel(
    const float* __restrict__ Wg, const float* __restrict__ Ug,
    __nv_bfloat16* __restrict__ Bhi, __nv_bfloat16* __restrict__ Blo)
{
    const int n = blockIdx.x;
    const int k = threadIdx.x;
    const float x = (k < Dn) ? Wg[n * Dn + k] : Ug[n * Dn + (k - Dn)];
    const __nv_bfloat16 hi = __float2bfloat16(x);
    Bhi[(size_t)n * Kn + k] = hi;
    Blo[(size_t)n * Kn + k] = __float2bfloat16(x - __bfloat162float(hi));
}

// ---------------------------------------------------------------------------
// Kernel 3: HMMA bf16x3 GEMM, CTA tile 64x256, 8 warps (each 64x32),
// cp.async double-buffered, XOR-swizzled smem, fused sigmoid-gate epilogue.
// ---------------------------------------------------------------------------
#define GT 256
// smem byte offsets (dynamic)
#define SA0 0
#define SB0 8192
#define SA1 40960
#define SB1 49152
#define SBIAS 81920
#define GSMEM (81920 + 1024)

// swizzled byte offset within a tile: row-major 128B rows, 16B chunks XORed
__device__ __forceinline__ uint32_t swz(int row, int k /*bf16 col*/) {
    return (uint32_t)(row * 128 + (((k >> 3) ^ (row & 7)) << 4) + (k & 7) * 2);
}

__global__ __launch_bounds__(GT, 1) void gemm_mma_kernel(
    const __nv_bfloat16* __restrict__ Ahi,
    const __nv_bfloat16* __restrict__ Alo,
    const __nv_bfloat16* __restrict__ Bhi,
    const __nv_bfloat16* __restrict__ Blo,
    const float* __restrict__ hA,
    const float* __restrict__ rA,
    const float* __restrict__ Wgb,
    const float* __restrict__ Ugb,
    const float* __restrict__ bg,
    const int*   __restrict__ lengths,
    float*       __restrict__ out)
{
    extern __shared__ char gsm[];
    const uint32_t sbase = smem_u32(gsm);

    const int tid  = threadIdx.x;
    const int w    = tid >> 5;        // 0..7
    const int lane = tid & 31;
    const int g    = lane >> 2;       // 0..7
    const int tg   = lane & 3;        // 0..3
    const int rbase = blockIdx.x * 64;
    const int n0    = w * 32;

    if (tid < Dn)
        *(float*)(gsm + SBIAS + tid * 4) = Wgb[tid] + Ugb[tid] + bg[tid];

    const uint32_t abuf[2] = { sbase + SA0, sbase + SA1 };
    const uint32_t bbuf[2] = { sbase + SB0, sbase + SB1 };
    const char*    abufp[2] = { gsm + SA0, gsm + SA1 };
    const char*    bbufp[2] = { gsm + SB0, gsm + SB1 };

    // chunk c: term = c>>3 (0:hi*hi 1:hi*lo 2:lo*hi), kc = c&7 (64-col slice)
    auto issue = [&](int c) {
        const int p    = c & 1;
        const int term = c >> 3;
        const int kc   = c & 7;
        const __nv_bfloat16* Asrc = (term == 2) ? Alo : Ahi;
        const __nv_bfloat16* Bsrc = (term == 1) ? Blo : Bhi;
        // A: 64x64 bf16 = 512 x 16B; 2 per thread
#pragma unroll
        for (int j = 0; j < 2; ++j) {
            const int v = tid + GT * j;
            const int row = v >> 3, seg = v & 7;
            cp16(abuf[p] + swz(row, seg * 8),
                 Asrc + (size_t)(rbase + row) * Kn + kc * 64 + seg * 8);
        }
        // B: 256x64 bf16 = 2048 x 16B; 8 per thread
#pragma unroll
        for (int j = 0; j < 8; ++j) {
            const int v = tid + GT * j;
            const int row = v >> 3, seg = v & 7;
            cp16(bbuf[p] + swz(row, seg * 8),
                 Bsrc + (size_t)row * Kn + kc * 64 + seg * 8);
        }
        cp_commit();
    };

    float acc[4][4][4] = {};   // [mt][nt][reg]

    issue(0);
#pragma unroll 1
    for (int c = 0; c < 24; ++c) {
        if (c < 23) { issue(c + 1); cp_wait<1>(); }
        else        { cp_wait<0>(); }
        __syncthreads();

        const char* As = abufp[c & 1];
        const char* Bs = bbufp[c & 1];

#pragma unroll
        for (int ks = 0; ks < 4; ++ks) {
            const int k0 = ks * 16 + tg * 2;
            const int k1 = k0 + 8;
            uint32_t af[4][4];
#pragma unroll
            for (int mt = 0; mt < 4; ++mt) {
                const int r0 = mt * 16 + g;
                af[mt][0] = *(const uint32_t*)(As + swz(r0,     k0));
                af[mt][1] = *(const uint32_t*)(As + swz(r0 + 8, k0));
                af[mt][2] = *(const uint32_t*)(As + swz(r0,     k1));
                af[mt][3] = *(const uint32_t*)(As + swz(r0 + 8, k1));
            }
            uint32_t bf[4][2];
#pragma unroll
            for (int nt = 0; nt < 4; ++nt) {
                const int n = n0 + nt * 8 + g;
                bf[nt][0] = *(const uint32_t*)(Bs + swz(n, k0));
                bf[nt][1] = *(const uint32_t*)(Bs + swz(n, k1));
            }
#pragma unroll
            for (int mt = 0; mt < 4; ++mt)
#pragma unroll
                for (int nt = 0; nt < 4; ++nt)
                    mma16816(acc[mt][nt][0], acc[mt][nt][1],
                             acc[mt][nt][2], acc[mt][nt][3],
                             af[mt][0], af[mt][1], af[mt][2], af[mt][3],
                             bf[nt][0], bf[nt][1]);
        }
        __syncthreads();
    }

    // Epilogue: d0,d1 -> (row g, cols d,d+1); d2,d3 -> (row g+8).
    const float* bias_s = (const float*)(gsm + SBIAS);
#pragma unroll
    for (int mt = 0; mt < 4; ++mt) {
        const int b0 = rbase + mt * 16 + g;
        const int b1 = b0 + 8;
        const int len0 = lengths[b0];
        const int len1 = lengths[b1];
#pragma unroll
        for (int nt = 0; nt < 4; ++nt) {
            const int d = n0 + nt * 8 + tg * 2;
            const float bz0 = bias_s[d], bz1 = bias_s[d + 1];

            const float2 rv0 = *(const float2*)&rA[(size_t)b0 * Dn + d];
            const float2 hv0 = *(const float2*)&hA[(size_t)b0 * Dn + d];
            const float2 rv1 = *(const float2*)&rA[(size_t)b1 * Dn + d];
            const float2 hv1 = *(const float2*)&hA[(size_t)b1 * Dn + d];

            float2 o0, o1;
            {
                const float z = acc[mt][nt][0] + bz0;
                const float gg = 1.f / (1.f + __expf(-z));
                o0.x = (len0 > 0) ? gg * rv0.x + (1.f - gg) * hv0.x : hv0.x;
            }
            {
                const float z = acc[mt][nt][1] + bz1;
                const float gg = 1.f / (1.f + __expf(-z));
                o0.y = (len0 > 0) ? gg * rv0.y + (1.f - gg) * hv0.y : hv0.y;
            }
            {
                const float z = acc[mt][nt][2] + bz0;
                const float gg = 1.f / (1.f + __expf(-z));
                o1.x = (len1 > 0) ? gg * rv1.x + (1.f - gg) * hv1.x : hv1.x;
            }
            {
                const float z = acc[mt][nt][3] + bz1;
                const float gg = 1.f / (1.f + __expf(-z));
                o1.y = (len1 > 0) ? gg * rv1.y + (1.f - gg) * hv1.y : hv1.y;
            }
            *(float2*)&out[(size_t)b0 * Dn + d] = o0;
            *(float2*)&out[(size_t)b1 * Dn + d] = o1;
        }
    }
}

// ---------------------------------------------------------------------------
extern "C" void kernel_launch(void* const* d_in, const int* in_sizes, int n_in,
                              void* d_out, int out_size)
{
    const float* h_tilde = (const float*)d_in[0];
    const float* mem     = (const float*)d_in[1];
    const int*   lengths = (const int*)  d_in[2];
    const float* Wg_w    = (const float*)d_in[3];
    const float* Wg_b    = (const float*)d_in[4];
    const float* Ug_w    = (const float*)d_in[5];
    const float* Ug_b    = (const float*)d_in[6];
    const float* b_g     = (const float*)d_in[7];
    float* out = (float*)d_out;

    float* r_ptr; __nv_bfloat16 *ahi, *alo, *bhi, *blo;
    cudaGetSymbolAddress((void**)&r_ptr, g_r);
    cudaGetSymbolAddress((void**)&ahi, g_Ahi);
    cudaGetSymbolAddress((void**)&alo, g_Alo);
    cudaGetSymbolAddress((void**)&bhi, g_Bhi);
    cudaGetSymbolAddress((void**)&blo, g_Blo);

    const int attn_smem = (Mn * Dn + Dn + Mn) * (int)sizeof(float);
    cudaFuncSetAttribute(attn_kernel,
                         cudaFuncAttributeMaxDynamicSharedMemorySize, attn_smem);
    cudaFuncSetAttribute(gemm_mma_kernel,
                         cudaFuncAttributeMaxDynamicSharedMemorySize, GSMEM);

    attn_kernel<<<Bn, 256, attn_smem>>>(h_tilde, mem, lengths, r_ptr, ahi, alo);
    wconv_kernel<<<Dn, Kn>>>(Wg_w, Ug_w, bhi, blo);
    gemm_mma_kernel<<<Bn / 64, GT, GSMEM>>>(ahi, alo, bhi, blo,
                                            h_tilde, r_ptr,
                                            Wg_b, Ug_b, b_g, lengths, out);
}

// round 9
// speedup vs baseline: 1.6018x; 1.1923x over previous
#include <cuda_runtime.h>
#include <cuda_bf16.h>
#include <cstdint>

#define Bn 8192
#define Mn 64
#define Dn 256
#define Kn 512

__device__ __align__(16) float         g_r  [(size_t)Bn * Dn];
__device__ __align__(16) __nv_bfloat16 g_Ahi[(size_t)Bn * Kn];
__device__ __align__(16) __nv_bfloat16 g_Alo[(size_t)Bn * Kn];
__device__ __align__(16) __nv_bfloat16 g_Bhi[(size_t)Dn * Kn];
__device__ __align__(16) __nv_bfloat16 g_Blo[(size_t)Dn * Kn];

// ---------------------------------------------------------------------------
__device__ __forceinline__ uint32_t smem_u32(const void* p) {
    uint32_t a;
    asm("{ .reg .u64 t; cvta.to.shared.u64 t, %1; cvt.u32.u64 %0, t; }"
        : "=r"(a) : "l"(p));
    return a;
}
__device__ __forceinline__ void cp16(uint32_t dst, const void* src) {
    asm volatile("cp.async.cg.shared.global [%0], [%1], 16;"
                 :: "r"(dst), "l"(src) : "memory");
}
__device__ __forceinline__ void cp_commit() {
    asm volatile("cp.async.commit_group;" ::: "memory");
}
template <int N>
__device__ __forceinline__ void cp_wait() {
    asm volatile("cp.async.wait_group %0;" :: "n"(N) : "memory");
}
__device__ __forceinline__ void mma16816(float& d0, float& d1, float& d2, float& d3,
                                         uint32_t a0, uint32_t a1, uint32_t a2,
                                         uint32_t a3, uint32_t b0, uint32_t b1) {
    asm volatile(
        "mma.sync.aligned.m16n8k16.row.col.f32.bf16.bf16.f32 "
        "{%0,%1,%2,%3}, {%4,%5,%6,%7}, {%8,%9}, {%0,%1,%2,%3};"
        : "+f"(d0), "+f"(d1), "+f"(d2), "+f"(d3)
        : "r"(a0), "r"(a1), "r"(a2), "r"(a3), "r"(b0), "r"(b1));
}

// ---------------------------------------------------------------------------
// Kernel 1: attention. cp.async staging (2 groups), overlapped scores,
// float4 LDS, bf16 hi/lo split epilogue.
// smem: mem[64*256] @0 (64KB), h[256] @65536, sc[64] @66560
// ---------------------------------------------------------------------------
#define ATTN_SMEM 66816

__global__ __launch_bounds__(256, 3) void attn_kernel(
    const float* __restrict__ h,
    const float* __restrict__ mem,
    const int*   __restrict__ lengths,
    float*       __restrict__ r_out,
    __nv_bfloat16* __restrict__ Ahi,
    __nv_bfloat16* __restrict__ Alo)
{
    extern __shared__ float smem[];
    float* mem_s = smem;
    float* h_s   = smem + Mn * Dn;
    float* sc    = h_s + Dn;
    const uint32_t sb = smem_u32(smem);

    const int b    = blockIdx.x;
    const int tid  = threadIdx.x;
    const int lane = tid & 31;
    const int warp = tid >> 5;

    // stage mem[b]: 4096 x 16B via cp.async, two groups (rows 0-31 / 32-63)
    const char* src = (const char*)(mem + (size_t)b * Mn * Dn);
#pragma unroll
    for (int j = 0; j < 8; ++j) {
        const int c = tid + 256 * j;
        cp16(sb + c * 16, src + (size_t)c * 16);
    }
    cp_commit();
#pragma unroll
    for (int j = 8; j < 16; ++j) {
        const int c = tid + 256 * j;
        cp16(sb + c * 16, src + (size_t)c * 16);
    }
    cp_commit();

    h_s[tid] = h[(size_t)b * Dn + tid];

    cp_wait<1>();
    __syncthreads();

    // scores rows 0..31 (warp w: rows 4w..4w+3) while rows 32..63 land
    const float4* hv4 = (const float4*)h_s;
#pragma unroll
    for (int j = 0; j < 4; ++j) {
        const int m = warp * 4 + j;
        const float4* row = (const float4*)(mem_s + m * Dn);
        float s = 0.f;
#pragma unroll
        for (int q = 0; q < 2; ++q) {
            const float4 a = row[lane * 2 + q];
            const float4 c = hv4[lane * 2 + q];
            s = fmaf(a.x, c.x, s); s = fmaf(a.y, c.y, s);
            s = fmaf(a.z, c.z, s); s = fmaf(a.w, c.w, s);
        }
#pragma unroll
        for (int off = 16; off; off >>= 1)
            s += __shfl_xor_sync(0xffffffffu, s, off);
        if (lane == 0) sc[m] = s;
    }

    cp_wait<0>();
    __syncthreads();

#pragma unroll
    for (int j = 0; j < 4; ++j) {
        const int m = 32 + warp * 4 + j;
        const float4* row = (const float4*)(mem_s + m * Dn);
        float s = 0.f;
#pragma unroll
        for (int q = 0; q < 2; ++q) {
            const float4 a = row[lane * 2 + q];
            const float4 c = hv4[lane * 2 + q];
            s = fmaf(a.x, c.x, s); s = fmaf(a.y, c.y, s);
            s = fmaf(a.z, c.z, s); s = fmaf(a.w, c.w, s);
        }
#pragma unroll
        for (int off = 16; off; off >>= 1)
            s += __shfl_xor_sync(0xffffffffu, s, off);
        if (lane == 0) sc[m] = s;
    }
    __syncthreads();

    // masked softmax (warp 0)
    if (warp == 0) {
        const int len = lengths[b];
        float a0 = (lane      < len) ? sc[lane]      : -1e9f;
        float a1 = (lane + 32 < len) ? sc[lane + 32] : -1e9f;
        float mx = fmaxf(a0, a1);
#pragma unroll
        for (int off = 16; off; off >>= 1)
            mx = fmaxf(mx, __shfl_xor_sync(0xffffffffu, mx, off));
        float e0 = __expf(a0 - mx);
        float e1 = __expf(a1 - mx);
        float s  = e0 + e1;
#pragma unroll
        for (int off = 16; off; off >>= 1)
            s += __shfl_xor_sync(0xffffffffu, s, off);
        const float inv = 1.f / s;
        sc[lane]      = e0 * inv;
        sc[lane + 32] = e1 * inv;
    }
    __syncthreads();

    // weighted sum: thread tid owns column tid (conflict-free scalar LDS)
    float acc = 0.f;
#pragma unroll
    for (int m = 0; m < Mn; ++m)
        acc = fmaf(sc[m], mem_s[m * Dn + tid], acc);
    r_out[(size_t)b * Dn + tid] = acc;

    // bf16 hi/lo splits of [h | r]
    {
        const float xh = h_s[tid];
        const __nv_bfloat16 hh = __float2bfloat16(xh);
        Ahi[(size_t)b * Kn + tid] = hh;
        Alo[(size_t)b * Kn + tid] = __float2bfloat16(xh - __bfloat162float(hh));
        const __nv_bfloat16 rh = __float2bfloat16(acc);
        Ahi[(size_t)b * Kn + Dn + tid] = rh;
        Alo[(size_t)b * Kn + Dn + tid] = __float2bfloat16(acc - __bfloat162float(rh));
    }
}

// ---------------------------------------------------------------------------
// Kernel 2: weight concat + bf16 hi/lo split.
// ---------------------------------------------------------------------------
__global__ __launch_bounds__(512) void wconv_kernel(
    const float* __restrict__ Wg, const float* __restrict__ Ug,
    __nv_bfloat16* __restrict__ Bhi, __nv_bfloat16* __restrict__ Blo)
{
    const int n = blockIdx.x;
    const int k = threadIdx.x;
    const float x = (k < Dn) ? Wg[n * Dn + k] : Ug[n * Dn + (k - Dn)];
    const __nv_bfloat16 hi = __float2bfloat16(x);
    Bhi[(size_t)n * Kn + k] = hi;
    Blo[(size_t)n * Kn + k] = __float2bfloat16(x - __bfloat162float(hi));
}

// ---------------------------------------------------------------------------
// Kernel 3: HMMA bf16x3 GEMM. CTA tile 64x128, grid (2,128)=256 CTAs,
// 8 warps each 64x16, 3-stage cp.async pipeline, fused epilogue.
// ---------------------------------------------------------------------------
#define GT 256
// smem: A 3x8KB @0, B 3x16KB @24576, bias(128f) @73728
#define SA(s) (8192u * (s))
#define SB(s) (24576u + 16384u * (s))
#define SBIAS 73728
#define GSMEM (73728 + 512)

__device__ __forceinline__ uint32_t swz(int row, int k /*bf16 col*/) {
    return (uint32_t)(row * 128 + (((k >> 3) ^ (row & 7)) << 4) + (k & 7) * 2);
}

__global__ __launch_bounds__(GT) void gemm_mma_kernel(
    const __nv_bfloat16* __restrict__ Ahi,
    const __nv_bfloat16* __restrict__ Alo,
    const __nv_bfloat16* __restrict__ Bhi,
    const __nv_bfloat16* __restrict__ Blo,
    const float* __restrict__ hA,
    const float* __restrict__ rA,
    const float* __restrict__ Wgb,
    const float* __restrict__ Ugb,
    const float* __restrict__ bg,
    const int*   __restrict__ lengths,
    float*       __restrict__ out)
{
    extern __shared__ char gsm[];
    const uint32_t sbase = smem_u32(gsm);

    const int tid  = threadIdx.x;
    const int w    = tid >> 5;
    const int lane = tid & 31;
    const int g    = lane >> 2;
    const int tg   = lane & 3;
    const int rbase = blockIdx.y * 64;
    const int cbase = blockIdx.x * 128;
    const int n0    = w * 16;

    if (tid < 128) {
        const int d = cbase + tid;
        *(float*)(gsm + SBIAS + tid * 4) = Wgb[d] + Ugb[d] + bg[d];
    }

    // chunk c: term = c>>3 (0:hi*hi 1:hi*lo 2:lo*hi), kc = c&7 (64-col slice)
    auto issue = [&](int c) {
        const int s    = c % 3;
        const int term = c >> 3;
        const int kc   = c & 7;
        const __nv_bfloat16* Asrc = (term == 2) ? Alo : Ahi;
        const __nv_bfloat16* Bsrc = (term == 1) ? Blo : Bhi;
        // A: 64x64 bf16 = 512 x 16B
#pragma unroll
        for (int j = 0; j < 2; ++j) {
            const int v = tid + GT * j;
            const int row = v >> 3, seg = v & 7;
            cp16(sbase + SA(s) + swz(row, seg * 8),
                 Asrc + (size_t)(rbase + row) * Kn + kc * 64 + seg * 8);
        }
        // B: 128x64 bf16 = 1024 x 16B
#pragma unroll
        for (int j = 0; j < 4; ++j) {
            const int v = tid + GT * j;
            const int row = v >> 3, seg = v & 7;
            cp16(sbase + SB(s) + swz(row, seg * 8),
                 Bsrc + (size_t)(cbase + row) * Kn + kc * 64 + seg * 8);
        }
        cp_commit();
    };

    float acc[4][2][4] = {};

    issue(0);
    issue(1);
#pragma unroll 1
    for (int c = 0; c < 24; ++c) {
        if (c < 22)      { issue(c + 2); cp_wait<2>(); }
        else if (c == 22) cp_wait<1>();
        else              cp_wait<0>();
        __syncthreads();

        const char* As = gsm + SA(c % 3);
        const char* Bs = gsm + SB(c % 3);

#pragma unroll
        for (int ks = 0; ks < 4; ++ks) {
            const int k0 = ks * 16 + tg * 2;
            const int k1 = k0 + 8;
            uint32_t af[4][4];
#pragma unroll
            for (int mt = 0; mt < 4; ++mt) {
                const int r0 = mt * 16 + g;
                af[mt][0] = *(const uint32_t*)(As + swz(r0,     k0));
                af[mt][1] = *(const uint32_t*)(As + swz(r0 + 8, k0));
                af[mt][2] = *(const uint32_t*)(As + swz(r0,     k1));
                af[mt][3] = *(const uint32_t*)(As + swz(r0 + 8, k1));
            }
            uint32_t bf[2][2];
#pragma unroll
            for (int nt = 0; nt < 2; ++nt) {
                const int n = n0 + nt * 8 + g;
                bf[nt][0] = *(const uint32_t*)(Bs + swz(n, k0));
                bf[nt][1] = *(const uint32_t*)(Bs + swz(n, k1));
            }
#pragma unroll
            for (int mt = 0; mt < 4; ++mt)
#pragma unroll
                for (int nt = 0; nt < 2; ++nt)
                    mma16816(acc[mt][nt][0], acc[mt][nt][1],
                             acc[mt][nt][2], acc[mt][nt][3],
                             af[mt][0], af[mt][1], af[mt][2], af[mt][3],
                             bf[nt][0], bf[nt][1]);
        }
        __syncthreads();
    }

    const float* bias_s = (const float*)(gsm + SBIAS);
#pragma unroll
    for (int mt = 0; mt < 4; ++mt) {
        const int b0 = rbase + mt * 16 + g;
        const int b1 = b0 + 8;
        const int len0 = lengths[b0];
        const int len1 = lengths[b1];
#pragma unroll
        for (int nt = 0; nt < 2; ++nt) {
            const int dl = n0 + nt * 8 + tg * 2;   // local col
            const int d  = cbase + dl;             // global col
            const float bz0 = bias_s[dl], bz1 = bias_s[dl + 1];

            const float2 rv0 = *(const float2*)&rA[(size_t)b0 * Dn + d];
            const float2 hv0 = *(const float2*)&hA[(size_t)b0 * Dn + d];
            const float2 rv1 = *(const float2*)&rA[(size_t)b1 * Dn + d];
            const float2 hv1 = *(const float2*)&hA[(size_t)b1 * Dn + d];

            float2 o0, o1;
            {
                const float z = acc[mt][nt][0] + bz0;
                const float gg = 1.f / (1.f + __expf(-z));
                o0.x = (len0 > 0) ? gg * rv0.x + (1.f - gg) * hv0.x : hv0.x;
            }
            {
                const float z = acc[mt][nt][1] + bz1;
                const float gg = 1.f / (1.f + __expf(-z));
                o0.y = (len0 > 0) ? gg * rv0.y + (1.f - gg) * hv0.y : hv0.y;
            }
            {
                const float z = acc[mt][nt][2] + bz0;
                const float gg = 1.f / (1.f + __expf(-z));
                o1.x = (len1 > 0) ? gg * rv1.x + (1.f - gg) * hv1.x : hv1.x;
            }
            {
                const float z = acc[mt][nt][3] + bz1;
                const float gg = 1.f / (1.f + __expf(-z));
                o1.y = (len1 > 0) ? gg * rv1.y + (1.f - gg) * hv1.y : hv1.y;
            }
            *(float2*)&out[(size_t)b0 * Dn + d] = o0;
            *(float2*)&out[(size_t)b1 * Dn + d] = o1;
        }
    }
}

// ---------------------------------------------------------------------------
extern "C" void kernel_launch(void* const* d_in, const int* in_sizes, int n_in,
                              void* d_out, int out_size)
{
    const float* h_tilde = (const float*)d_in[0];
    const float* mem     = (const float*)d_in[1];
    const int*   lengths = (const int*)  d_in[2];
    const float* Wg_w    = (const float*)d_in[3];
    const float* Wg_b    = (const float*)d_in[4];
    const float* Ug_w    = (const float*)d_in[5];
    const float* Ug_b    = (const float*)d_in[6];
    const float* b_g     = (const float*)d_in[7];
    float* out = (float*)d_out;

    float* r_ptr; __nv_bfloat16 *ahi, *alo, *bhi, *blo;
    cudaGetSymbolAddress((void**)&r_ptr, g_r);
    cudaGetSymbolAddress((void**)&ahi, g_Ahi);
    cudaGetSymbolAddress((void**)&alo, g_Alo);
    cudaGetSymbolAddress((void**)&bhi, g_Bhi);
    cudaGetSymbolAddress((void**)&blo, g_Blo);

    cudaFuncSetAttribute(attn_kernel,
                         cudaFuncAttributeMaxDynamicSharedMemorySize, ATTN_SMEM);
    cudaFuncSetAttribute(gemm_mma_kernel,
                         cudaFuncAttributeMaxDynamicSharedMemorySize, GSMEM);

    attn_kernel<<<Bn, 256, ATTN_SMEM>>>(h_tilde, mem, lengths, r_ptr, ahi, alo);
    wconv_kernel<<<Dn, Kn>>>(Wg_w, Ug_w, bhi, blo);

    dim3 grid(2, Bn / 64);   // 256 CTAs
    gemm_mma_kernel<<<grid, GT, GSMEM>>>(ahi, alo, bhi, blo,
                                         h_tilde, r_ptr,
                                         Wg_b, Ug_b, b_g, lengths, out);
}